// round 1
// baseline (speedup 1.0000x reference)
#include <cuda_runtime.h>
#include <math.h>

// Shapes (fixed): B=2, S=2048, E=1024, H=16, D=64
// Scratch: K,V in [B*H, S, D] layout; attention output in [B*S, E] layout.
static __device__ float g_K[2 * 16 * 2048 * 64];
static __device__ float g_V[2 * 16 * 2048 * 64];
static __device__ float g_O[2 * 2048 * 1024];

__device__ __forceinline__ float fast_exp2(float x) {
    float y;
    asm("ex2.approx.ftz.f32 %0, %1;" : "=f"(y) : "f"(x));
    return y;
}

// ---------------------------------------------------------------------------
// SGEMM body: C[m,n] = sum_k A[m,k] * W[n,k]   (TN: both operands K-major)
// Tile 128x128x16, 256 threads, 8x8 per thread.
// remap=1: write into [B,H,S,D] scratch layout (proj). remap=0: row-major N=1024.
// ---------------------------------------------------------------------------
__device__ __forceinline__ void sgemm_body(const float* __restrict__ A,
                                           const float* __restrict__ W,
                                           float* __restrict__ C,
                                           int remap) {
    __shared__ float As[16][132];
    __shared__ float Bs[16][132];
    const int K = 1024;
    const int bm = blockIdx.y * 128;
    const int bn = blockIdx.x * 128;
    const int tid = threadIdx.x;
    const int tx = tid & 15;
    const int ty = tid >> 4;

    float acc[8][8];
#pragma unroll
    for (int i = 0; i < 8; i++)
#pragma unroll
        for (int j = 0; j < 8; j++) acc[i][j] = 0.0f;

    for (int k0 = 0; k0 < K; k0 += 16) {
#pragma unroll
        for (int it = 0; it < 2; it++) {
            int f = tid + it * 256;       // 512 float4 loads per operand
            int row = f >> 2;             // 0..127
            int kc = (f & 3) << 2;        // 0,4,8,12
            float4 va = *reinterpret_cast<const float4*>(
                A + (size_t)(bm + row) * K + k0 + kc);
            As[kc + 0][row] = va.x;
            As[kc + 1][row] = va.y;
            As[kc + 2][row] = va.z;
            As[kc + 3][row] = va.w;
            float4 vb = *reinterpret_cast<const float4*>(
                W + (size_t)(bn + row) * K + k0 + kc);
            Bs[kc + 0][row] = vb.x;
            Bs[kc + 1][row] = vb.y;
            Bs[kc + 2][row] = vb.z;
            Bs[kc + 3][row] = vb.w;
        }
        __syncthreads();
#pragma unroll
        for (int k = 0; k < 16; k++) {
            float4 a0 = *reinterpret_cast<const float4*>(&As[k][ty * 8]);
            float4 a1 = *reinterpret_cast<const float4*>(&As[k][ty * 8 + 4]);
            float4 b0 = *reinterpret_cast<const float4*>(&Bs[k][tx * 8]);
            float4 b1 = *reinterpret_cast<const float4*>(&Bs[k][tx * 8 + 4]);
            float a[8] = {a0.x, a0.y, a0.z, a0.w, a1.x, a1.y, a1.z, a1.w};
            float b[8] = {b0.x, b0.y, b0.z, b0.w, b1.x, b1.y, b1.z, b1.w};
#pragma unroll
            for (int i = 0; i < 8; i++)
#pragma unroll
                for (int j = 0; j < 8; j++)
                    acc[i][j] = fmaf(a[i], b[j], acc[i][j]);
        }
        __syncthreads();
    }

    if (remap) {
        // C[((b*16+h)*2048+s)*64+d], m=b*2048+s, n=h*64+d
#pragma unroll
        for (int i = 0; i < 8; i++) {
            int m = bm + ty * 8 + i;
            int b = m >> 11;
            int s = m & 2047;
#pragma unroll
            for (int j4 = 0; j4 < 8; j4 += 4) {
                int n = bn + tx * 8 + j4;
                int h = n >> 6;
                int d = n & 63;
                float4 v = make_float4(acc[i][j4], acc[i][j4 + 1],
                                       acc[i][j4 + 2], acc[i][j4 + 3]);
                *reinterpret_cast<float4*>(
                    C + ((size_t)((b << 4) + h) * 2048 + s) * 64 + d) = v;
            }
        }
    } else {
#pragma unroll
        for (int i = 0; i < 8; i++) {
            int m = bm + ty * 8 + i;
#pragma unroll
            for (int j4 = 0; j4 < 8; j4 += 4) {
                float4 v = make_float4(acc[i][j4], acc[i][j4 + 1],
                                       acc[i][j4 + 2], acc[i][j4 + 3]);
                *reinterpret_cast<float4*>(C + (size_t)m * 1024 + bn + tx * 8 +
                                           j4) = v;
            }
        }
    }
}

// Fused K/V projection: grid.z = 0 -> K (Wk), 1 -> V (Wv)
__global__ __launch_bounds__(256) void proj_kernel(const float* __restrict__ x,
                                                   const float* __restrict__ Wk,
                                                   const float* __restrict__ Wv) {
    const float* W = (blockIdx.z == 0) ? Wk : Wv;
    float* C = (blockIdx.z == 0) ? g_K : g_V;
    sgemm_body(x, W, C, 1);
}

// Output projection: g_O @ Wo^T -> d_out
__global__ __launch_bounds__(256) void oproj_kernel(const float* __restrict__ Wo,
                                                    float* __restrict__ out) {
    sgemm_body(g_O, Wo, out, 0);
}

// ---------------------------------------------------------------------------
// Attention: per (b,h), logits = K V^T * (-32), softmax rows, out = P V.
// Flash-style: Br=128 query rows per block, iterate 16 key blocks of Bc=128.
// SMEM (floats): sKt[64][132] d-major K, sVd[64][132] d-major V,
//                sVk[128][68] key-major V, sP[128][132] probabilities.
// ---------------------------------------------------------------------------
#define SKT_OFF 0
#define SVD_OFF 8448
#define SVK_OFF 16896
#define SP_OFF 25600
#define ATTN_SMEM_BYTES (42496 * 4)

__global__ __launch_bounds__(256, 1) void attn_kernel() {
    extern __shared__ float sm[];
    float* sKt = sm + SKT_OFF;
    float* sVd = sm + SVD_OFF;
    float* sVk = sm + SVK_OFF;
    float* sP = sm + SP_OFF;

    const int tid = threadIdx.x;
    const int tx = tid & 15;
    const int ty = tid >> 4;
    const int hb = blockIdx.y;       // b*16 + h
    const int r0 = blockIdx.x * 128; // query row block
    const float* Kh = g_K + (size_t)hb * 2048 * 64;
    const float* Vh = g_V + (size_t)hb * 2048 * 64;
    const float SC = -32.0f * 1.4426950408889634f; // SCALE * log2(e)

    // Load K tile [128 rows][64 d] -> sKt[d][row]
#pragma unroll
    for (int it = 0; it < 8; it++) {
        int f = tid + it * 256;
        int row = f >> 4;
        int d4 = (f & 15) << 2;
        float4 v = *reinterpret_cast<const float4*>(Kh + (size_t)(r0 + row) * 64 + d4);
        sKt[(d4 + 0) * 132 + row] = v.x;
        sKt[(d4 + 1) * 132 + row] = v.y;
        sKt[(d4 + 2) * 132 + row] = v.z;
        sKt[(d4 + 3) * 132 + row] = v.w;
    }

    float m_i[8], l_i[8], o[8][4];
#pragma unroll
    for (int i = 0; i < 8; i++) {
        m_i[i] = -INFINITY;
        l_i[i] = 0.0f;
#pragma unroll
        for (int j = 0; j < 4; j++) o[i][j] = 0.0f;
    }

    for (int c0 = 0; c0 < 2048; c0 += 128) {
        __syncthreads(); // prior-iter readers of sVk/sVd/sP done (also covers sKt fill)
        // Load V tile into both layouts
#pragma unroll
        for (int it = 0; it < 8; it++) {
            int f = tid + it * 256;
            int key = f >> 4;
            int d4 = (f & 15) << 2;
            float4 v = *reinterpret_cast<const float4*>(Vh + (size_t)(c0 + key) * 64 + d4);
            *reinterpret_cast<float4*>(&sVk[key * 68 + d4]) = v;
            sVd[(d4 + 0) * 132 + key] = v.x;
            sVd[(d4 + 1) * 132 + key] = v.y;
            sVd[(d4 + 2) * 132 + key] = v.z;
            sVd[(d4 + 3) * 132 + key] = v.w;
        }
        __syncthreads();

        // S[128x128] = K V^T : thread computes 8 rows x 8 keys
        float s[8][8];
#pragma unroll
        for (int i = 0; i < 8; i++)
#pragma unroll
            for (int j = 0; j < 8; j++) s[i][j] = 0.0f;
#pragma unroll
        for (int k = 0; k < 64; k++) {
            float4 a0 = *reinterpret_cast<const float4*>(&sKt[k * 132 + ty * 8]);
            float4 a1 = *reinterpret_cast<const float4*>(&sKt[k * 132 + ty * 8 + 4]);
            float4 b0 = *reinterpret_cast<const float4*>(&sVd[k * 132 + tx * 8]);
            float4 b1 = *reinterpret_cast<const float4*>(&sVd[k * 132 + tx * 8 + 4]);
            float a[8] = {a0.x, a0.y, a0.z, a0.w, a1.x, a1.y, a1.z, a1.w};
            float b[8] = {b0.x, b0.y, b0.z, b0.w, b1.x, b1.y, b1.z, b1.w};
#pragma unroll
            for (int i = 0; i < 8; i++)
#pragma unroll
                for (int j = 0; j < 8; j++)
                    s[i][j] = fmaf(a[i], b[j], s[i][j]);
        }

        // Scale (negative! scale BEFORE max) and online softmax in base-2
#pragma unroll
        for (int i = 0; i < 8; i++)
#pragma unroll
            for (int j = 0; j < 8; j++) s[i][j] *= SC;

#pragma unroll
        for (int i = 0; i < 8; i++) {
            float mx = s[i][0];
#pragma unroll
            for (int j = 1; j < 8; j++) mx = fmaxf(mx, s[i][j]);
#pragma unroll
            for (int off = 1; off < 16; off <<= 1)
                mx = fmaxf(mx, __shfl_xor_sync(0xffffffffu, mx, off));
            float mn = fmaxf(m_i[i], mx);
            float al = fast_exp2(m_i[i] - mn);
            m_i[i] = mn;
            float rs = 0.0f;
#pragma unroll
            for (int j = 0; j < 8; j++) {
                float p = fast_exp2(s[i][j] - mn);
                s[i][j] = p;
                rs += p;
            }
#pragma unroll
            for (int off = 1; off < 16; off <<= 1)
                rs += __shfl_xor_sync(0xffffffffu, rs, off);
            l_i[i] = l_i[i] * al + rs;
#pragma unroll
            for (int j = 0; j < 4; j++) o[i][j] *= al;
        }

        // Store P row-major
#pragma unroll
        for (int i = 0; i < 8; i++) {
            *reinterpret_cast<float4*>(&sP[(ty * 8 + i) * 132 + tx * 8]) =
                make_float4(s[i][0], s[i][1], s[i][2], s[i][3]);
            *reinterpret_cast<float4*>(&sP[(ty * 8 + i) * 132 + tx * 8 + 4]) =
                make_float4(s[i][4], s[i][5], s[i][6], s[i][7]);
        }
        __syncthreads();

        // O[128x64] += P @ V : thread accumulates 8 rows x 4 dims
#pragma unroll 8
        for (int k2 = 0; k2 < 128; k2 += 4) {
            float areg[8][4];
#pragma unroll
            for (int i = 0; i < 8; i++) {
                float4 t = *reinterpret_cast<const float4*>(&sP[(ty * 8 + i) * 132 + k2]);
                areg[i][0] = t.x; areg[i][1] = t.y; areg[i][2] = t.z; areg[i][3] = t.w;
            }
#pragma unroll
            for (int kk = 0; kk < 4; kk++) {
                float4 bv = *reinterpret_cast<const float4*>(&sVk[(k2 + kk) * 68 + tx * 4]);
#pragma unroll
                for (int i = 0; i < 8; i++) {
                    o[i][0] = fmaf(areg[i][kk], bv.x, o[i][0]);
                    o[i][1] = fmaf(areg[i][kk], bv.y, o[i][1]);
                    o[i][2] = fmaf(areg[i][kk], bv.z, o[i][2]);
                    o[i][3] = fmaf(areg[i][kk], bv.w, o[i][3]);
                }
            }
        }
    }

    // Normalize + write to g_O in [B,S,E] layout (head h at cols h*64..)
    const int b = hb >> 4;
    const int h = hb & 15;
#pragma unroll
    for (int i = 0; i < 8; i++) {
        float inv = 1.0f / l_i[i];
        int row = r0 + ty * 8 + i;
        float4 v = make_float4(o[i][0] * inv, o[i][1] * inv, o[i][2] * inv,
                               o[i][3] * inv);
        *reinterpret_cast<float4*>(g_O + ((size_t)(b * 2048 + row)) * 1024 +
                                   h * 64 + tx * 4) = v;
    }
}

extern "C" void kernel_launch(void* const* d_in, const int* in_sizes, int n_in,
                              void* d_out, int out_size) {
    const float* x = (const float*)d_in[0];
    // d_in[1] = Wq (unused by the reference's dataflow)
    const float* Wk = (const float*)d_in[2];
    const float* Wv = (const float*)d_in[3];
    const float* Wo = (const float*)d_in[4];
    float* out = (float*)d_out;

    // K/V projections (Q is dead code in the reference)
    proj_kernel<<<dim3(8, 32, 2), 256>>>(x, Wk, Wv);

    // Attention
    cudaFuncSetAttribute(attn_kernel, cudaFuncAttributeMaxDynamicSharedMemorySize,
                         ATTN_SMEM_BYTES);
    attn_kernel<<<dim3(16, 32), 256, ATTN_SMEM_BYTES>>>();

    // Output projection
    oproj_kernel<<<dim3(8, 32), 256>>>(Wo, out);
}

// round 3
// speedup vs baseline: 1.0035x; 1.0035x over previous
#include <cuda_runtime.h>
#include <math.h>
#include <stdint.h>

// Shapes (fixed): B=2, S=2048, E=1024, H=16, D=64
static __device__ float g_K[2 * 16 * 2048 * 64];
static __device__ float g_V[2 * 16 * 2048 * 64];
static __device__ float g_O[2 * 2048 * 1024];

__device__ __forceinline__ float fast_exp2(float x) {
    float y;
    asm("ex2.approx.ftz.f32 %0, %1;" : "=f"(y) : "f"(x));
    return y;
}

__device__ __forceinline__ uint32_t tf32_of(float x) {
    uint32_t r;
    asm("cvt.rna.tf32.f32 %0, %1;" : "=r"(r) : "f"(x));
    return r;
}

__device__ __forceinline__ void mma16n8k8(float c[4], const uint32_t a[4],
                                          const uint32_t b[2]) {
    asm volatile(
        "mma.sync.aligned.m16n8k8.row.col.f32.tf32.tf32.f32 "
        "{%0,%1,%2,%3}, {%4,%5,%6,%7}, {%8,%9}, {%0,%1,%2,%3};"
        : "+f"(c[0]), "+f"(c[1]), "+f"(c[2]), "+f"(c[3])
        : "r"(a[0]), "r"(a[1]), "r"(a[2]), "r"(a[3]), "r"(b[0]), "r"(b[1]));
}

#define SW128(o) ((o) ^ (((o) >> 3) & 0x70))

// ---------------------------------------------------------------------------
// 3xTF32 mma.sync GEMM: C[m,n] = sum_k A[m,k]*W[n,k]. CTA tile 128x128, K=1024
// in 32 steps of 32. SMEM holds fragment-major tf32 hi/lo copies, double-buffer.
// Warp layout: 8 warps = 4(M) x 2(N); warp tile 32x64 = 2x8 m16n8k8 tiles.
// SMEM buffer: A_hi 16K | A_lo 16K | B_hi 16K | B_lo 16K  (x2 buffers = 128KB)
// ---------------------------------------------------------------------------
#define AHI 0
#define ALO 16384
#define BHI 32768
#define BLO 49152
#define BUFSZ 65536
#define GM_SMEM_BYTES (2 * BUFSZ)

struct Pref {
    float4 a[4];
    float4 b[4];
};

__device__ __forceinline__ void gm_load(const float* __restrict__ A,
                                        const float* __restrict__ W, int bm,
                                        int bn, int k0, int tid, Pref& p) {
#pragma unroll
    for (int it = 0; it < 4; it++) {
        int f = tid + it * 256;
        int r = f >> 3;
        int c4 = f & 7;
        p.a[it] = *reinterpret_cast<const float4*>(A + (size_t)(bm + r) * 1024 +
                                                   k0 + c4 * 4);
        p.b[it] = *reinterpret_cast<const float4*>(W + (size_t)(bn + r) * 1024 +
                                                   k0 + c4 * 4);
    }
}

__device__ __forceinline__ void st_frag(char* smb, const Pref& p, int tid) {
#pragma unroll
    for (int it = 0; it < 4; it++) {
        int f = tid + it * 256;
        int r = f >> 3;
        int c4 = f & 7;
        int k8 = c4 >> 1;
        int cc = c4 & 1; // c>>2
        const float va[4] = {p.a[it].x, p.a[it].y, p.a[it].z, p.a[it].w};
        const float vb[4] = {p.b[it].x, p.b[it].y, p.b[it].z, p.b[it].w};
        // A: tile = r>>4, lane = (r&7)*4+e, slot = cc*2 + ((r>>3)&1)
        {
            uint32_t tile = (uint32_t)(r >> 4);
            uint32_t base = (uint32_t)(k8 * 8 + tile) * 512 +
                            (uint32_t)((r & 7) * 4) * 16 +
                            (uint32_t)(cc * 2 + ((r >> 3) & 1)) * 4;
#pragma unroll
            for (int e = 0; e < 4; e++) {
                uint32_t off = SW128(base + e * 16);
                uint32_t hi = tf32_of(va[e]);
                uint32_t lo = tf32_of(va[e] - __uint_as_float(hi));
                *reinterpret_cast<uint32_t*>(smb + AHI + off) = hi;
                *reinterpret_cast<uint32_t*>(smb + ALO + off) = lo;
            }
        }
        // B: n = r: tile = r>>3, lane = (r&7)*4 + e, slot = cc
        {
            uint32_t tile = (uint32_t)(r >> 3);
            uint32_t base = (uint32_t)(k8 * 16 + tile) * 256 +
                            (uint32_t)((r & 7) * 4) * 8 + (uint32_t)cc * 4;
#pragma unroll
            for (int e = 0; e < 4; e++) {
                uint32_t off = SW128(base + e * 8);
                uint32_t hi = tf32_of(vb[e]);
                uint32_t lo = tf32_of(vb[e] - __uint_as_float(hi));
                *reinterpret_cast<uint32_t*>(smb + BHI + off) = hi;
                *reinterpret_cast<uint32_t*>(smb + BLO + off) = lo;
            }
        }
    }
}

__device__ void gemm_mma_body(const float* __restrict__ A,
                              const float* __restrict__ W,
                              float* __restrict__ Cout, int remap) {
    extern __shared__ char smc[];
    const int tid = threadIdx.x;
    const int lane = tid & 31;
    const int wid = tid >> 5;
    const int warpM = wid & 3;
    const int warpN = wid >> 2;
    const int bm = blockIdx.y * 128;
    const int bn = blockIdx.x * 128;

    float c[2][8][4];
#pragma unroll
    for (int i = 0; i < 2; i++)
#pragma unroll
        for (int j = 0; j < 8; j++)
#pragma unroll
            for (int q = 0; q < 4; q++) c[i][j][q] = 0.0f;

    Pref p;
    gm_load(A, W, bm, bn, 0, tid, p);

    for (int kt = 0; kt < 32; kt++) {
        char* smb = smc + (kt & 1) * BUFSZ;
        st_frag(smb, p, tid);
        __syncthreads();
        if (kt < 31) gm_load(A, W, bm, bn, (kt + 1) * 32, tid, p);

#pragma unroll
        for (int k8 = 0; k8 < 4; k8++) {
            uint32_t ah[2][4], al[2][4], bh[8][2], bl[8][2];
#pragma unroll
            for (int tm = 0; tm < 2; tm++) {
                uint32_t tile = warpM * 2 + tm;
                uint32_t off = SW128((uint32_t)(k8 * 8 + tile) * 512 + lane * 16);
                uint4 h = *reinterpret_cast<const uint4*>(smb + AHI + off);
                ah[tm][0] = h.x; ah[tm][1] = h.y; ah[tm][2] = h.z; ah[tm][3] = h.w;
                uint4 l = *reinterpret_cast<const uint4*>(smb + ALO + off);
                al[tm][0] = l.x; al[tm][1] = l.y; al[tm][2] = l.z; al[tm][3] = l.w;
            }
#pragma unroll
            for (int tn = 0; tn < 8; tn++) {
                uint32_t tile = warpN * 8 + tn;
                uint32_t off = SW128((uint32_t)(k8 * 16 + tile) * 256 + lane * 8);
                uint2 h = *reinterpret_cast<const uint2*>(smb + BHI + off);
                bh[tn][0] = h.x; bh[tn][1] = h.y;
                uint2 l = *reinterpret_cast<const uint2*>(smb + BLO + off);
                bl[tn][0] = l.x; bl[tn][1] = l.y;
            }
#pragma unroll
            for (int tm = 0; tm < 2; tm++)
#pragma unroll
                for (int tn = 0; tn < 8; tn++) {
                    mma16n8k8(c[tm][tn], ah[tm], bh[tn]);
                    mma16n8k8(c[tm][tn], ah[tm], bl[tn]);
                    mma16n8k8(c[tm][tn], al[tm], bh[tn]);
                }
        }
        __syncthreads();
    }

    // Epilogue: c[tm][tn] rows = bm+warpM*32+tm*16+{g, g+8}, cols = bn+warpN*64+tn*8+t4*2+{0,1}
    const int g = lane >> 2;
    const int t4 = lane & 3;
#pragma unroll
    for (int tm = 0; tm < 2; tm++) {
#pragma unroll
        for (int tn = 0; tn < 8; tn++) {
            int row0 = bm + warpM * 32 + tm * 16 + g;
            int col = bn + warpN * 64 + tn * 8 + t4 * 2;
#pragma unroll
            for (int hrow = 0; hrow < 2; hrow++) {
                int m = row0 + hrow * 8;
                float2 v = make_float2(c[tm][tn][2 * hrow], c[tm][tn][2 * hrow + 1]);
                if (remap) {
                    int bb = m >> 11;
                    int s = m & 2047;
                    int h = col >> 6;
                    int d = col & 63;
                    *reinterpret_cast<float2*>(
                        Cout + ((size_t)((bb << 4) + h) * 2048 + s) * 64 + d) = v;
                } else {
                    *reinterpret_cast<float2*>(Cout + (size_t)m * 1024 + col) = v;
                }
            }
        }
    }
}

__global__ __launch_bounds__(256, 1) void proj_mma_kernel(const float* __restrict__ x,
                                                          const float* __restrict__ Wk,
                                                          const float* __restrict__ Wv) {
    const float* W = (blockIdx.z == 0) ? Wk : Wv;
    float* C = (blockIdx.z == 0) ? g_K : g_V;
    gemm_mma_body(x, W, C, 1);
}

__global__ __launch_bounds__(256, 1) void oproj_mma_kernel(const float* __restrict__ Wo,
                                                           float* __restrict__ out) {
    gemm_mma_body(g_O, Wo, out, 0);
}

// ---------------------------------------------------------------------------
// Attention (fp32 flash-style, unchanged): logits = K V^T * (-32), softmax, P V.
// ---------------------------------------------------------------------------
#define SKT_OFF 0
#define SVD_OFF 8448
#define SVK_OFF 16896
#define SP_OFF 25600
#define ATTN_SMEM_BYTES (42496 * 4)

__global__ __launch_bounds__(256, 1) void attn_kernel() {
    extern __shared__ float sm[];
    float* sKt = sm + SKT_OFF;
    float* sVd = sm + SVD_OFF;
    float* sVk = sm + SVK_OFF;
    float* sP = sm + SP_OFF;

    const int tid = threadIdx.x;
    const int tx = tid & 15;
    const int ty = tid >> 4;
    const int hb = blockIdx.y;
    const int r0 = blockIdx.x * 128;
    const float* Kh = g_K + (size_t)hb * 2048 * 64;
    const float* Vh = g_V + (size_t)hb * 2048 * 64;
    const float SC = -32.0f * 1.4426950408889634f;

#pragma unroll
    for (int it = 0; it < 8; it++) {
        int f = tid + it * 256;
        int row = f >> 4;
        int d4 = (f & 15) << 2;
        float4 v = *reinterpret_cast<const float4*>(Kh + (size_t)(r0 + row) * 64 + d4);
        sKt[(d4 + 0) * 132 + row] = v.x;
        sKt[(d4 + 1) * 132 + row] = v.y;
        sKt[(d4 + 2) * 132 + row] = v.z;
        sKt[(d4 + 3) * 132 + row] = v.w;
    }

    float m_i[8], l_i[8], o[8][4];
#pragma unroll
    for (int i = 0; i < 8; i++) {
        m_i[i] = -INFINITY;
        l_i[i] = 0.0f;
#pragma unroll
        for (int j = 0; j < 4; j++) o[i][j] = 0.0f;
    }

    for (int c0 = 0; c0 < 2048; c0 += 128) {
        __syncthreads();
#pragma unroll
        for (int it = 0; it < 8; it++) {
            int f = tid + it * 256;
            int key = f >> 4;
            int d4 = (f & 15) << 2;
            float4 v = *reinterpret_cast<const float4*>(Vh + (size_t)(c0 + key) * 64 + d4);
            *reinterpret_cast<float4*>(&sVk[key * 68 + d4]) = v;
            sVd[(d4 + 0) * 132 + key] = v.x;
            sVd[(d4 + 1) * 132 + key] = v.y;
            sVd[(d4 + 2) * 132 + key] = v.z;
            sVd[(d4 + 3) * 132 + key] = v.w;
        }
        __syncthreads();

        float s[8][8];
#pragma unroll
        for (int i = 0; i < 8; i++)
#pragma unroll
            for (int j = 0; j < 8; j++) s[i][j] = 0.0f;
#pragma unroll
        for (int k = 0; k < 64; k++) {
            float4 a0 = *reinterpret_cast<const float4*>(&sKt[k * 132 + ty * 8]);
            float4 a1 = *reinterpret_cast<const float4*>(&sKt[k * 132 + ty * 8 + 4]);
            float4 b0 = *reinterpret_cast<const float4*>(&sVd[k * 132 + tx * 8]);
            float4 b1 = *reinterpret_cast<const float4*>(&sVd[k * 132 + tx * 8 + 4]);
            float a[8] = {a0.x, a0.y, a0.z, a0.w, a1.x, a1.y, a1.z, a1.w};
            float b[8] = {b0.x, b0.y, b0.z, b0.w, b1.x, b1.y, b1.z, b1.w};
#pragma unroll
            for (int i = 0; i < 8; i++)
#pragma unroll
                for (int j = 0; j < 8; j++)
                    s[i][j] = fmaf(a[i], b[j], s[i][j]);
        }

#pragma unroll
        for (int i = 0; i < 8; i++)
#pragma unroll
            for (int j = 0; j < 8; j++) s[i][j] *= SC;

#pragma unroll
        for (int i = 0; i < 8; i++) {
            float mx = s[i][0];
#pragma unroll
            for (int j = 1; j < 8; j++) mx = fmaxf(mx, s[i][j]);
#pragma unroll
            for (int off = 1; off < 16; off <<= 1)
                mx = fmaxf(mx, __shfl_xor_sync(0xffffffffu, mx, off));
            float mn = fmaxf(m_i[i], mx);
            float al = fast_exp2(m_i[i] - mn);
            m_i[i] = mn;
            float rs = 0.0f;
#pragma unroll
            for (int j = 0; j < 8; j++) {
                float pp = fast_exp2(s[i][j] - mn);
                s[i][j] = pp;
                rs += pp;
            }
#pragma unroll
            for (int off = 1; off < 16; off <<= 1)
                rs += __shfl_xor_sync(0xffffffffu, rs, off);
            l_i[i] = l_i[i] * al + rs;
#pragma unroll
            for (int j = 0; j < 4; j++) o[i][j] *= al;
        }

#pragma unroll
        for (int i = 0; i < 8; i++) {
            *reinterpret_cast<float4*>(&sP[(ty * 8 + i) * 132 + tx * 8]) =
                make_float4(s[i][0], s[i][1], s[i][2], s[i][3]);
            *reinterpret_cast<float4*>(&sP[(ty * 8 + i) * 132 + tx * 8 + 4]) =
                make_float4(s[i][4], s[i][5], s[i][6], s[i][7]);
        }
        __syncthreads();

#pragma unroll 8
        for (int k2 = 0; k2 < 128; k2 += 4) {
            float areg[8][4];
#pragma unroll
            for (int i = 0; i < 8; i++) {
                float4 t = *reinterpret_cast<const float4*>(&sP[(ty * 8 + i) * 132 + k2]);
                areg[i][0] = t.x; areg[i][1] = t.y; areg[i][2] = t.z; areg[i][3] = t.w;
            }
#pragma unroll
            for (int kk = 0; kk < 4; kk++) {
                float4 bv = *reinterpret_cast<const float4*>(&sVk[(k2 + kk) * 68 + tx * 4]);
#pragma unroll
                for (int i = 0; i < 8; i++) {
                    o[i][0] = fmaf(areg[i][kk], bv.x, o[i][0]);
                    o[i][1] = fmaf(areg[i][kk], bv.y, o[i][1]);
                    o[i][2] = fmaf(areg[i][kk], bv.z, o[i][2]);
                    o[i][3] = fmaf(areg[i][kk], bv.w, o[i][3]);
                }
            }
        }
    }

    const int b = hb >> 4;
    const int h = hb & 15;
#pragma unroll
    for (int i = 0; i < 8; i++) {
        float inv = 1.0f / l_i[i];
        int row = r0 + ty * 8 + i;
        float4 v = make_float4(o[i][0] * inv, o[i][1] * inv, o[i][2] * inv,
                               o[i][3] * inv);
        *reinterpret_cast<float4*>(g_O + ((size_t)(b * 2048 + row)) * 1024 +
                                   h * 64 + tx * 4) = v;
    }
}

extern "C" void kernel_launch(void* const* d_in, const int* in_sizes, int n_in,
                              void* d_out, int out_size) {
    const float* x = (const float*)d_in[0];
    // d_in[1] = Wq (dead code in the reference dataflow)
    const float* Wk = (const float*)d_in[2];
    const float* Wv = (const float*)d_in[3];
    const float* Wo = (const float*)d_in[4];
    float* out = (float*)d_out;

    cudaFuncSetAttribute(proj_mma_kernel, cudaFuncAttributeMaxDynamicSharedMemorySize,
                         GM_SMEM_BYTES);
    cudaFuncSetAttribute(oproj_mma_kernel, cudaFuncAttributeMaxDynamicSharedMemorySize,
                         GM_SMEM_BYTES);
    cudaFuncSetAttribute(attn_kernel, cudaFuncAttributeMaxDynamicSharedMemorySize,
                         ATTN_SMEM_BYTES);

    // K/V projections via 3xTF32 mma.sync
    proj_mma_kernel<<<dim3(8, 32, 2), 256, GM_SMEM_BYTES>>>(x, Wk, Wv);

    // Attention (fp32)
    attn_kernel<<<dim3(16, 32), 256, ATTN_SMEM_BYTES>>>();

    // Output projection via 3xTF32 mma.sync
    oproj_mma_kernel<<<dim3(8, 32), 256, GM_SMEM_BYTES>>>(Wo, out);
}